// round 11
// baseline (speedup 1.0000x reference)
#include <cuda_runtime.h>

#define NS       8192
#define NC       1024
#define NK       4
#define TILE     32            // channels per block tile
#define THREADS  128           // samples per block (1 per thread)
#define PAD      4
#define WROW     40            // words per comp window row
#define CSTRIDE  168           // region stride per copy; 168 % 32 == 8 -> disjoint bank groups
#define SROW     36            // staging row stride (16B-aligned, conflict-free)

__global__ void __launch_bounds__(THREADS)
smf_kernel(const float* __restrict__ comp,      // [4, 1024]
           const float* __restrict__ contrib,   // [8192, 4]
           const float* __restrict__ shift,     // [8192, 4]
           float* __restrict__ out)             // [8192, 1024]
{
    // 4 window copies, copy c shifted by +c words; each row 4-aligned bases only
    __shared__ __align__(16) float sc[3 * CSTRIDE + NK * WROW + 8];
    __shared__ __align__(16) float st[THREADS * SROW];   // staging tile

    const int tid  = threadIdx.x;
    const int tile = blockIdx.x & 31;           // 32 channel tiles
    const int grp  = blockIdx.x >> 5;           // 64 sample groups
    const int c0   = tile * TILE;
    const int s    = grp * THREADS + tid;

    // prefetch per-sample params first (hide LDG latency under window fill)
    const float4 sh4 = __ldg((const float4*)(shift   + s * NK));
    const float4 cn4 = __ldg((const float4*)(contrib + s * NK));

    // ---- fill 4 copies: copy c, row k, word w = comp[k, c0-4+c+w] (OOB=0) ----
    for (int idx = tid; idx < 4 * NK * WROW; idx += THREADS) {
        const int cpy = idx / (NK * WROW);
        const int rem = idx - cpy * (NK * WROW);
        const int k = rem / WROW, w = rem - k * WROW;
        const int j = c0 - PAD + cpy + w;
        sc[cpy * CSTRIDE + k * WROW + w] = (j >= 0 && j < NC) ? comp[k * NC + j] : 0.0f;
    }

    const float shv[NK] = { sh4.x, sh4.y, sh4.z, sh4.w };
    const float cnv[NK] = { cn4.x, cn4.y, cn4.z, cn4.w };

    float a[NK], b[NK];
    int   base[NK];
    #pragma unroll
    for (int k = 0; k < NK; k++) {
        const float sh = shv[k];
        const float cn = cnv[k];
        int fi = (int)floorf(sh);               // in [-4, 4]
        fi = max(-4, min(3, fi));               // shift==4.0 folds into fr=1
        const float fr = sh - (float)fi;
        b[k] = cn * fr;                         // weight of tap fi+1
        a[k] = cn - b[k];                       // cn*(1-fr)
        const int c = fi & 3;                   // copy index
        base[k] = c * CSTRIDE + k * WROW + (fi + 4 - c);   // 4-aligned: 0 or 4
    }
    __syncthreads();

    // ---- main: per 4 channels per k: 1 LDS.128 (1 wavefront) + 8 FFMA ----
    float4 u[NK];
    #pragma unroll
    for (int k = 0; k < NK; k++) u[k] = *(const float4*)&sc[base[k]];

    float4* myst = (float4*)(st + tid * SROW);
    #pragma unroll
    for (int q = 0; q < TILE / 4; q++) {        // channels 4q .. 4q+3
        float a0 = 0.f, a1 = 0.f, a2 = 0.f, a3 = 0.f;
        #pragma unroll
        for (int k = 0; k < NK; k++) {
            const float4 v = *(const float4*)&sc[base[k] + 4 * q + 4];
            a0 += a[k] * u[k].x + b[k] * u[k].y;
            a1 += a[k] * u[k].y + b[k] * u[k].z;
            a2 += a[k] * u[k].z + b[k] * u[k].w;
            a3 += a[k] * u[k].w + b[k] * v.x;
            u[k] = v;
        }
        myst[q] = make_float4(a0, a1, a2, a3);  // STS.128, conflict-free
    }
    __syncthreads();

    // ---- coalesced tile store: 128 samples x 8 float4 each ----
    #pragma unroll
    for (int j2 = 0; j2 < 8; j2++) {
        const int flat = j2 * THREADS + tid;    // 0..1023
        const int sl   = flat >> 3;             // local sample 0..127
        const int q    = flat & 7;
        const float4 v = ((const float4*)st)[sl * (SROW / 4) + q];
        ((float4*)out)[(size_t)(grp * THREADS + sl) * (NC / 4) + (c0 >> 2) + q] = v;
    }
}

extern "C" void kernel_launch(void* const* d_in, const int* in_sizes, int n_in,
                              void* d_out, int out_size)
{
    // inputs [8192,1024] (ignored), components [4,1024],
    // contributions [8192,4], shift [8192,4]
    const float* comp    = (const float*)d_in[1];
    const float* contrib = (const float*)d_in[2];
    const float* shift   = (const float*)d_in[3];
    float* out           = (float*)d_out;

    smf_kernel<<<32 * 64, THREADS>>>(comp, contrib, shift, out);   // 2048 blocks
}

// round 12
// speedup vs baseline: 1.0619x; 1.0619x over previous
#include <cuda_runtime.h>
#include <cuda.h>
#include <cstdint>

#define NS       8192
#define NC       1024
#define NK       4
#define TILE     32            // channels per block tile
#define THREADS  128           // samples per round (1 per thread)
#define SPT      2             // rounds per block -> grid 1024 (single wave)
#define PAD      4
#define WROW     40            // words per comp window row
#define OFF1     172           // +1-shifted copy offset (no 0 mod 32 aliasing)

__global__ void __launch_bounds__(THREADS)
smf_kernel(const float* __restrict__ comp,      // [4, 1024]
           const float* __restrict__ contrib,   // [8192, 4]
           const float* __restrict__ shift,     // [8192, 4]
           const __grid_constant__ CUtensorMap tmap)   // out [8192, 1024] f32, SW128
{
    __shared__ __align__(16)   float sc[OFF1 + NK * WROW]; // copy0 + copy1(+1 word)
    __shared__ __align__(1024) float st[THREADS * TILE];   // 16KB SW128-swizzled tile

    const int tid   = threadIdx.x;
    const int tile  = blockIdx.x & 31;          // 32 channel tiles
    const int grp   = blockIdx.x >> 5;          // 32 sample groups
    const int c0    = tile * TILE;
    const int sbase = grp * (THREADS * SPT);

    // prefetch per-sample params for both rounds (hide LDG under window fill)
    float4 shp[SPT], cnp[SPT];
    #pragma unroll
    for (int r = 0; r < SPT; r++) {
        shp[r] = __ldg((const float4*)(shift   + (size_t)(sbase + r * THREADS + tid) * NK));
        cnp[r] = __ldg((const float4*)(contrib + (size_t)(sbase + r * THREADS + tid) * NK));
    }

    // ---- fill windows: copy0[k][w]=comp[k,c0-4+w], copy1[k][w]=comp[k,c0-3+w] ----
    for (int idx = tid; idx < 2 * NK * WROW; idx += THREADS) {
        const int cpy = idx >= NK * WROW;
        const int rem = idx - cpy * (NK * WROW);
        const int k = rem / WROW, w = rem - k * WROW;
        const int j = c0 - PAD + w + cpy;
        sc[cpy * OFF1 + k * WROW + w] = (j >= 0 && j < NC) ? comp[k * NC + j] : 0.0f;
    }
    __syncthreads();

    const uint32_t st_u32 = (uint32_t)__cvta_generic_to_shared(st);
    float4* st4 = (float4*)st;
    const int xorl = tid & 7;                   // SW128 column xor for this row

    #pragma unroll
    for (int r = 0; r < SPT; r++) {
        if (r > 0) {                            // staging reuse: prior TMA store done
            if (tid == 0) asm volatile("cp.async.bulk.wait_group 0;" ::: "memory");
            __syncthreads();
        }

        const float shv[NK] = { shp[r].x, shp[r].y, shp[r].z, shp[r].w };
        const float cnv[NK] = { cnp[r].x, cnp[r].y, cnp[r].z, cnp[r].w };

        float a[NK], b[NK];
        int   base[NK];
        #pragma unroll
        for (int k = 0; k < NK; k++) {
            const float sh = shv[k];
            const float cn = cnv[k];
            int   fi = (int)floorf(sh);         // in [-4, 4]
            float fr = sh - (float)fi;
            if (fi > 3)  { fr += (float)(fi - 3); fi = 3; }   // shift==4.0 edge
            if (fi < -4) { fi = -4; }
            b[k] = cn * fr;                     // weight of tap fi+1
            a[k] = cn - b[k];                   // cn*(1-fr)
            const bool odd = (fi & 1) != 0;     // parity-matched 2-aligned base
            base[k] = (odd ? OFF1 : 0) + k * WROW + (odd ? (fi + 3) : (fi + 4));
        }

        // ---- main: per 2 channels per k: 1 LDS.64 + 4 FFMA (rolling) ----
        float2 u[NK];
        #pragma unroll
        for (int k = 0; k < NK; k++) u[k] = *(const float2*)&sc[base[k]];

        float4 buf;
        #pragma unroll
        for (int ip = 0; ip < TILE / 2; ip++) { // channels 2ip, 2ip+1
            float a0 = 0.f, a1 = 0.f;
            #pragma unroll
            for (int k = 0; k < NK; k++) {
                const float2 v = *(const float2*)&sc[base[k] + 2 * ip + 2];
                a0 += a[k] * u[k].x + b[k] * u[k].y;
                a1 += a[k] * u[k].y + b[k] * v.x;
                u[k] = v;
            }
            if (ip & 1) {                        // SW128-swizzled STS.128, conflict-free
                buf.z = a0; buf.w = a1;
                st4[tid * 8 + ((ip >> 1) ^ xorl)] = buf;
            } else { buf.x = a0; buf.y = a1; }
        }

        // ---- one TMA tensor store for the whole [32 x 128] tile ----
        asm volatile("fence.proxy.async.shared::cta;" ::: "memory");
        __syncthreads();
        if (tid == 0) {
            asm volatile(
                "cp.async.bulk.tensor.2d.global.shared::cta.tile.bulk_group "
                "[%0, {%1, %2}], [%3];"
                :: "l"(&tmap), "r"(c0), "r"(sbase + r * THREADS), "r"(st_u32)
                : "memory");
            asm volatile("cp.async.bulk.commit_group;" ::: "memory");
        }
    }
    if (tid == 0) asm volatile("cp.async.bulk.wait_group 0;" ::: "memory");
}

// ---- host: tensormap via runtime driver-entry-point (no -lcuda link) ----
typedef CUresult (*PFN_encodeTiled)(
    CUtensorMap*, CUtensorMapDataType, cuuint32_t, void*,
    const cuuint64_t*, const cuuint64_t*, const cuuint32_t*, const cuuint32_t*,
    CUtensorMapInterleave, CUtensorMapSwizzle, CUtensorMapL2promotion,
    CUtensorMapFloatOOBfill);

static PFN_encodeTiled get_encoder()
{
    static PFN_encodeTiled fn = nullptr;
    if (!fn) {
        void* p = nullptr;
        cudaDriverEntryPointQueryResult qr;
#if CUDART_VERSION >= 12050
        cudaGetDriverEntryPointByVersion("cuTensorMapEncodeTiled", &p, 12000,
                                         cudaEnableDefault, &qr);
#else
        cudaGetDriverEntryPoint("cuTensorMapEncodeTiled", &p,
                                cudaEnableDefault, &qr);
#endif
        fn = (PFN_encodeTiled)p;
    }
    return fn;
}

extern "C" void kernel_launch(void* const* d_in, const int* in_sizes, int n_in,
                              void* d_out, int out_size)
{
    // inputs [8192,1024] (ignored), components [4,1024],
    // contributions [8192,4], shift [8192,4]
    const float* comp    = (const float*)d_in[1];
    const float* contrib = (const float*)d_in[2];
    const float* shift   = (const float*)d_in[3];

    CUtensorMap tmap;
    {
        cuuint64_t dims[2]    = { NC, NS };           // inner = channels
        cuuint64_t strides[1] = { NC * sizeof(float) };
        cuuint32_t box[2]     = { TILE, THREADS };    // 32 ch x 128 samples
        cuuint32_t estr[2]    = { 1, 1 };
        get_encoder()(&tmap, CU_TENSOR_MAP_DATA_TYPE_FLOAT32, 2, d_out,
                      dims, strides, box, estr,
                      CU_TENSOR_MAP_INTERLEAVE_NONE, CU_TENSOR_MAP_SWIZZLE_128B,
                      CU_TENSOR_MAP_L2_PROMOTION_L2_128B,
                      CU_TENSOR_MAP_FLOAT_OOB_FILL_NONE);
    }

    smf_kernel<<<32 * (NS / (THREADS * SPT)), THREADS>>>(comp, contrib, shift, tmap);
}

// round 13
// speedup vs baseline: 1.1811x; 1.1122x over previous
#include <cuda_runtime.h>
#include <cuda.h>
#include <cstdint>

#define NS       8192
#define NC       1024
#define NK       4
#define TILE     32            // channels per block tile
#define THREADS  128           // samples per block (1 per thread)
#define PAD      4
#define WROW     40            // words per comp window row
#define OFF1     172           // +1-shifted copy offset (no 0 mod 32 aliasing)

__global__ void __launch_bounds__(THREADS)
smf_kernel(const float* __restrict__ comp,      // [4, 1024]
           const float* __restrict__ contrib,   // [8192, 4]
           const float* __restrict__ shift,     // [8192, 4]
           const __grid_constant__ CUtensorMap tmap)   // out [8192, 1024] f32, SW128
{
    __shared__ __align__(16)   float sc[OFF1 + NK * WROW]; // copy0 + copy1(+1 word)
    __shared__ __align__(1024) float st[THREADS * TILE];   // 16KB SW128-swizzled tile

    const int tid  = threadIdx.x;
    const int tile = blockIdx.x & 31;           // 32 channel tiles
    const int grp  = blockIdx.x >> 5;           // 64 sample groups
    const int c0   = tile * TILE;
    const int s0   = grp * THREADS;

    // prefetch per-sample params (hide LDG latency under window fill)
    const float4 sh4 = __ldg((const float4*)(shift   + (size_t)(s0 + tid) * NK));
    const float4 cn4 = __ldg((const float4*)(contrib + (size_t)(s0 + tid) * NK));

    // ---- fill windows: copy0[k][w]=comp[k,c0-4+w], copy1[k][w]=comp[k,c0-3+w] ----
    for (int idx = tid; idx < 2 * NK * WROW; idx += THREADS) {
        const int cpy = idx >= NK * WROW;
        const int rem = idx - cpy * (NK * WROW);
        const int k = rem / WROW, w = rem - k * WROW;
        const int j = c0 - PAD + w + cpy;
        sc[cpy * OFF1 + k * WROW + w] = (j >= 0 && j < NC) ? comp[k * NC + j] : 0.0f;
    }

    const float shv[NK] = { sh4.x, sh4.y, sh4.z, sh4.w };
    const float cnv[NK] = { cn4.x, cn4.y, cn4.z, cn4.w };

    float a[NK], b[NK];
    int   base[NK];
    #pragma unroll
    for (int k = 0; k < NK; k++) {
        const float sh = shv[k];
        const float cn = cnv[k];
        int   fi = (int)floorf(sh);             // in [-4, 4]
        float fr = sh - (float)fi;
        if (fi > 3)  { fr += (float)(fi - 3); fi = 3; }   // shift==4.0 edge
        if (fi < -4) { fi = -4; }
        b[k] = cn * fr;                         // weight of tap fi+1
        a[k] = cn - b[k];                       // cn*(1-fr)
        const bool odd = (fi & 1) != 0;         // parity-matched 2-aligned base
        base[k] = (odd ? OFF1 : 0) + k * WROW + (odd ? (fi + 3) : (fi + 4));
    }
    __syncthreads();

    // ---- main: per 2 channels per k: 1 LDS.64 + 4 FFMA (rolling) ----
    float2 u[NK];
    #pragma unroll
    for (int k = 0; k < NK; k++) u[k] = *(const float2*)&sc[base[k]];

    float4* st4 = (float4*)st;
    const int xorl = tid & 7;                   // SW128 column xor for this row
    float4 buf;
    #pragma unroll
    for (int ip = 0; ip < TILE / 2; ip++) {     // channels 2ip, 2ip+1
        float a0 = 0.f, a1 = 0.f;
        #pragma unroll
        for (int k = 0; k < NK; k++) {
            const float2 v = *(const float2*)&sc[base[k] + 2 * ip + 2];
            a0 += a[k] * u[k].x + b[k] * u[k].y;
            a1 += a[k] * u[k].y + b[k] * v.x;
            u[k] = v;
        }
        if (ip & 1) {                            // SW128-swizzled STS.128, conflict-free
            buf.z = a0; buf.w = a1;
            st4[tid * 8 + ((ip >> 1) ^ xorl)] = buf;
        } else { buf.x = a0; buf.y = a1; }
    }

    // ---- one TMA tensor store for the whole [128 x 32] tile ----
    asm volatile("fence.proxy.async.shared::cta;" ::: "memory");
    __syncthreads();
    if (tid == 0) {
        const uint32_t st_u32 = (uint32_t)__cvta_generic_to_shared(st);
        asm volatile(
            "cp.async.bulk.tensor.2d.global.shared::cta.tile.bulk_group "
            "[%0, {%1, %2}], [%3];"
            :: "l"(&tmap), "r"(c0), "r"(s0), "r"(st_u32)
            : "memory");
        asm volatile("cp.async.bulk.commit_group;" ::: "memory");
        asm volatile("cp.async.bulk.wait_group 0;" ::: "memory");
    }
}

// ---- host: tensormap via runtime driver-entry-point (no -lcuda link) ----
typedef CUresult (*PFN_encodeTiled)(
    CUtensorMap*, CUtensorMapDataType, cuuint32_t, void*,
    const cuuint64_t*, const cuuint64_t*, const cuuint32_t*, const cuuint32_t*,
    CUtensorMapInterleave, CUtensorMapSwizzle, CUtensorMapL2promotion,
    CUtensorMapFloatOOBfill);

static PFN_encodeTiled get_encoder()
{
    static PFN_encodeTiled fn = nullptr;
    if (!fn) {
        void* p = nullptr;
        cudaDriverEntryPointQueryResult qr;
#if CUDART_VERSION >= 12050
        cudaGetDriverEntryPointByVersion("cuTensorMapEncodeTiled", &p, 12000,
                                         cudaEnableDefault, &qr);
#else
        cudaGetDriverEntryPoint("cuTensorMapEncodeTiled", &p,
                                cudaEnableDefault, &qr);
#endif
        fn = (PFN_encodeTiled)p;
    }
    return fn;
}

extern "C" void kernel_launch(void* const* d_in, const int* in_sizes, int n_in,
                              void* d_out, int out_size)
{
    // inputs [8192,1024] (ignored), components [4,1024],
    // contributions [8192,4], shift [8192,4]
    const float* comp    = (const float*)d_in[1];
    const float* contrib = (const float*)d_in[2];
    const float* shift   = (const float*)d_in[3];

    CUtensorMap tmap;
    {
        cuuint64_t dims[2]    = { NC, NS };           // inner = channels
        cuuint64_t strides[1] = { NC * sizeof(float) };
        cuuint32_t box[2]     = { TILE, THREADS };    // 32 ch x 128 samples
        cuuint32_t estr[2]    = { 1, 1 };
        get_encoder()(&tmap, CU_TENSOR_MAP_DATA_TYPE_FLOAT32, 2, d_out,
                      dims, strides, box, estr,
                      CU_TENSOR_MAP_INTERLEAVE_NONE, CU_TENSOR_MAP_SWIZZLE_128B,
                      CU_TENSOR_MAP_L2_PROMOTION_L2_128B,
                      CU_TENSOR_MAP_FLOAT_OOB_FILL_NONE);
    }

    smf_kernel<<<32 * (NS / THREADS), THREADS>>>(comp, contrib, shift, tmap);  // 2048
}